// round 13
// baseline (speedup 1.0000x reference)
#include <cuda_runtime.h>
#include <cuda_bf16.h>
#include <cstddef>

// Problem constants (from reference)
#define NFRAMES 8
#define NLOC    4096
#define NALL    8192
#define NNEI    256
#define NTYPES  4
#define NSPLINE 1024

static constexpr int THREADS   = 512;  // 16 warps/CTA, 3 CTAs/SM
static constexpr int WARPS     = THREADS / 32;
static constexpr int CHUNKS    = 14;   // chunks per (frame,type) bin -> 448 CTAs (~3/SM)

// Device-global scratch (allocation-free)
__device__ int    g_counts[NFRAMES * NTYPES];
__device__ int    g_lists [NFRAMES * NTYPES * NLOC];
__device__ float4 g_pack  [NFRAMES * NALL];          // (x,y,z,bitcast(type)) per atom

// ---------------- Pre-pass A: pack coords+type into float4 ----------------
__global__ __launch_bounds__(1024, 1)
void pack_kernel(const float* __restrict__ coord,    // (NFRAMES, NALL, 3)
                 const int*   __restrict__ atype)    // (NFRAMES, NALL)
{
    const int f   = blockIdx.x;
    const int tid = threadIdx.x;
    const float* cf = coord + (size_t)f * NALL * 3;
    const int*   af = atype + (size_t)f * NALL;
    for (int a = tid; a < NALL; a += 1024) {
        float x = cf[a * 3 + 0];
        float y = cf[a * 3 + 1];
        float z = cf[a * 3 + 2];
        int   t = af[a];
        g_pack[(size_t)f * NALL + a] = make_float4(x, y, z, __int_as_float(t));
    }
}

// ---------------- Pre-pass B: bin local atoms by their own type ----------------
__global__ __launch_bounds__(1024, 1)
void bin_by_type_kernel(const int* __restrict__ atype) // (NFRAMES, NALL)
{
    const int f   = blockIdx.x;
    const int tid = threadIdx.x;
    __shared__ int s_hist[NTYPES];
    __shared__ int s_off [NTYPES];

    if (tid < NTYPES) { s_hist[tid] = 0; }
    __syncthreads();

    const int* af = atype + (size_t)f * NALL; // local atoms are the first NLOC
    for (int a = tid; a < NLOC; a += 1024)
        atomicAdd(&s_hist[af[a]], 1);
    __syncthreads();

    if (tid < NTYPES) {
        g_counts[f * NTYPES + tid] = s_hist[tid];
        s_off[tid] = 0;
    }
    __syncthreads();

    for (int a = tid; a < NLOC; a += 1024) {
        const int t    = af[a];
        const int slot = atomicAdd(&s_off[t], 1);
        g_lists[(f * NTYPES + t) * NLOC + slot] = a;
    }
}

// ---------------- Main kernel ----------------
// Dynamic smem: s_tab float4[NTYPES*NSPLINE] = 64KB -> 3 CTAs/SM, 48 warps.
__global__ __launch_bounds__(THREADS, 3)
void pairtab_energy_kernel(const int*    __restrict__ nlist,   // (NFRAMES, NLOC, NNEI)
                           const float4* __restrict__ tab,     // (NTYPES,NTYPES,NSPLINE) float4
                           float*        __restrict__ out)     // (NFRAMES, NLOC)
{
    extern __shared__ float4 s_tab[];    // [NTYPES * NSPLINE]

    const int f     = blockIdx.y;
    const int t     = blockIdx.x / CHUNKS;   // i_type this CTA serves
    const int chunk = blockIdx.x % CHUNKS;
    const int tid   = threadIdx.x;

    // ---- Stage tab[t] : NTYPES*NSPLINE float4 = 64KB (coalesced) ----
    {
        const float4* tf = tab + (size_t)t * NTYPES * NSPLINE;
        for (int i = tid; i < NTYPES * NSPLINE; i += THREADS)
            s_tab[i] = tf[i];
    }
    __syncthreads();

    const int lane = tid & 31;
    const int wid  = tid >> 5;

    const int  cnt   = g_counts[f * NTYPES + t];
    const int  m     = (cnt + CHUNKS - 1) / CHUNKS;
    const int  start = chunk * m;
    const int  end   = min(start + m, cnt);
    const int* list  = g_lists + (f * NTYPES + t) * NLOC;

    const float4* pack = g_pack + (size_t)f * NALL;
    const int4*   nlb  = reinterpret_cast<const int4*>(nlist)
                       + (size_t)f * NLOC * (NNEI / 4);

    int k = start + wid;
    if (k < end) {
        // Prime: atom k's nlist in flight.
        int  atom = list[k];
        int4 p0   = nlb[atom * (NNEI / 4) + lane];
        int4 p1   = nlb[atom * (NNEI / 4) + 32 + lane];

        while (k < end) {
            const int  atom_cur = atom;
            const int4 c0 = p0;
            const int4 c1 = p1;
            const float4 pi = __ldg(&pack[atom_cur]);

            // Prefetch NEXT atom's nlist before the body.
            const int k2 = k + WARPS;
            if (k2 < end) {
                atom = list[k2];
                p0   = nlb[atom * (NNEI / 4) + lane];
                p1   = nlb[atom * (NNEI / 4) + 32 + lane];
            }

            const int js[8] = { c0.x, c0.y, c0.z, c0.w,
                                c1.x, c1.y, c1.z, c1.w };

            float acc = 0.0f;
            #pragma unroll
            for (int i = 0; i < 8; ++i) {
                const int  j    = js[i];
                const bool jval = (j >= 0);
                const int  jj   = jval ? j : 0;

                const float4 pj = __ldg(&pack[jj]);
                const float dx = __fadd_rn(pi.x, -pj.x);
                const float dy = __fadd_rn(pi.y, -pj.y);
                const float dz = __fadd_rn(pi.z, -pj.z);
                // Reference association (verified R5): (dx^2 + dz^2) + dy^2,
                // fully uncontracted, then * 50.0f (XLA reciprocal of 0.02f).
                const float sxz = __fadd_rn(__fmul_rn(dx, dx), __fmul_rn(dz, dz));
                const float r2  = __fadd_rn(sxz, __fmul_rn(dy, dy));
                const float rr  = __fsqrt_rn(r2);
                const float uu  = __fmul_rn(rr, 50.0f);
                const int   idx = (int)uu;          // trunc, uu >= 0

                const bool  v    = jval && (idx < NSPLINE);
                const int   ci   = min(idx, NSPLINE - 1);
                const float frac = __fadd_rn(uu, -(float)idx);
                const int   tj   = __float_as_int(pj.w);

                const float4 cc = s_tab[tj * NSPLINE + ci];
                float e = fmaf(cc.w, frac, cc.z);
                e = fmaf(e, frac, cc.y);
                e = fmaf(e, frac, cc.x);
                acc += v ? e : 0.0f;
            }

            // Warp reduction
            #pragma unroll
            for (int o = 16; o > 0; o >>= 1)
                acc += __shfl_xor_sync(0xffffffffu, acc, o);

            if (lane == 0)
                out[(size_t)f * NLOC + atom_cur] = 0.5f * acc;

            k = k2;
        }
    }
}

extern "C" void kernel_launch(void* const* d_in, const int* in_sizes, int n_in,
                              void* d_out, int out_size)
{
    const float*  coord = (const float*)  d_in[0]; // (8, 8192, 3) f32
    const int*    atype = (const int*)    d_in[1]; // (8, 8192) i32
    const int*    nlist = (const int*)    d_in[2]; // (8, 4096, 256) i32
    const float4* tab   = (const float4*) d_in[3]; // (4, 4, 1024, 4) f32 -> float4
    float*        out   = (float*)        d_out;   // (8, 4096) f32

    const int smem_bytes = NTYPES * NSPLINE * (int)sizeof(float4); // 65536
    static bool attr_set = false;
    if (!attr_set) {
        cudaFuncSetAttribute(pairtab_energy_kernel,
                             cudaFuncAttributeMaxDynamicSharedMemorySize, smem_bytes);
        attr_set = true;
    }

    pack_kernel<<<NFRAMES, 1024>>>(coord, atype);
    bin_by_type_kernel<<<NFRAMES, 1024>>>(atype);

    dim3 grid(NTYPES * CHUNKS, NFRAMES);   // (56, 8) = 448 CTAs
    pairtab_energy_kernel<<<grid, THREADS, smem_bytes>>>(nlist, tab, out);
}

// round 14
// speedup vs baseline: 1.0798x; 1.0798x over previous
#include <cuda_runtime.h>
#include <cuda_bf16.h>
#include <cstddef>

// Problem constants (from reference)
#define NFRAMES 8
#define NLOC    4096
#define NALL    8192
#define NNEI    256
#define NTYPES  4
#define NSPLINE 1024

static constexpr int THREADS = 1024;  // 32 warps/CTA, 2 CTAs/SM -> 64 warps
static constexpr int WARPS   = THREADS / 32;
static constexpr int CHUNKS  = 9;     // grid (36, 8) = 288 CTAs ~= 2 waves-free fit

// Device-global scratch (allocation-free)
__device__ int    g_counts[NFRAMES * NTYPES];
__device__ int    g_lists [NFRAMES * NTYPES * NLOC];
__device__ float4 g_pack  [NFRAMES * NALL];          // (x,y,z,bitcast(type))

// ---------------- Pre-pass A: pack coords+type into float4 (wide grid) ------
__global__ __launch_bounds__(512, 2)
void pack_kernel(const float* __restrict__ coord,    // (NFRAMES, NALL, 3)
                 const int*   __restrict__ atype)    // (NFRAMES, NALL)
{
    // Zero the bin counters for this launch (graph replays reuse globals).
    if (blockIdx.x == 0 && threadIdx.x < NFRAMES * NTYPES)
        g_counts[threadIdx.x] = 0;

    const int f    = blockIdx.x >> 3;        // 8 CTAs per frame
    const int part = blockIdx.x & 7;
    const int base = part * (NALL / 8);      // 1024 atoms per CTA

    const float* cf = coord + (size_t)f * NALL * 3;
    const int*   af = atype + (size_t)f * NALL;
    for (int a = base + threadIdx.x; a < base + NALL / 8; a += 512) {
        float x = cf[a * 3 + 0];
        float y = cf[a * 3 + 1];
        float z = cf[a * 3 + 2];
        int   t = af[a];
        g_pack[(size_t)f * NALL + a] = make_float4(x, y, z, __int_as_float(t));
    }
}

// ---------------- Pre-pass B: bin local atoms by their own type -------------
__global__ __launch_bounds__(1024, 1)
void bin_by_type_kernel(const int* __restrict__ atype) // (NFRAMES, NALL)
{
    const int f   = blockIdx.x;
    const int tid = threadIdx.x;
    __shared__ int s_off[NTYPES];

    if (tid < NTYPES) s_off[tid] = 0;
    __syncthreads();

    const int* af = atype + (size_t)f * NALL; // local atoms = first NLOC
    for (int a = tid; a < NLOC; a += 1024) {
        const int t    = af[a];
        const int slot = atomicAdd(&s_off[t], 1);
        g_lists[(f * NTYPES + t) * NLOC + slot] = a;
    }
    __syncthreads();
    if (tid < NTYPES)
        g_counts[f * NTYPES + tid] = s_off[tid];
}

// ---------------- Main kernel ----------------
// Dynamic smem: s_tab float4[NTYPES*NSPLINE] = 64KB.
// __launch_bounds__(1024, 2): 2 CTAs/SM (64 warps), forces <=32 regs/thread.
__global__ __launch_bounds__(THREADS, 2)
void pairtab_energy_kernel(const int*    __restrict__ nlist,   // (NFRAMES, NLOC, NNEI)
                           const float4* __restrict__ tab,     // (NTYPES,NTYPES,NSPLINE) f4
                           float*        __restrict__ out)     // (NFRAMES, NLOC)
{
    extern __shared__ float4 s_tab[];    // [NTYPES * NSPLINE]

    const int f     = blockIdx.y;
    const int t     = blockIdx.x / CHUNKS;   // i_type this CTA serves
    const int chunk = blockIdx.x % CHUNKS;
    const int tid   = threadIdx.x;

    // ---- Stage tab[t] : 64KB (coalesced) ----
    {
        const float4* tf = tab + (size_t)t * NTYPES * NSPLINE;
        for (int i = tid; i < NTYPES * NSPLINE; i += THREADS)
            s_tab[i] = tf[i];
    }
    __syncthreads();

    const int lane = tid & 31;
    const int wid  = tid >> 5;

    const int  cnt   = g_counts[f * NTYPES + t];
    const int  m     = (cnt + CHUNKS - 1) / CHUNKS;
    const int  start = chunk * m;
    const int  end   = min(start + m, cnt);
    const int* list  = g_lists + (f * NTYPES + t) * NLOC;

    const float4* pack = g_pack + (size_t)f * NALL;
    const int4*   nlb  = reinterpret_cast<const int4*>(nlist)
                       + (size_t)f * NLOC * (NNEI / 4);

    for (int k = start + wid; k < end; k += WARPS) {
        const int atom = list[k];
        const float4 pi = __ldg(&pack[atom]);

        const int4 n0 = nlb[atom * (NNEI / 4) + lane];
        const int4 n1 = nlb[atom * (NNEI / 4) + 32 + lane];
        const int js[8] = { n0.x, n0.y, n0.z, n0.w,
                            n1.x, n1.y, n1.z, n1.w };

        float acc = 0.0f;
        #pragma unroll
        for (int i = 0; i < 8; ++i) {
            const int  j    = js[i];
            const bool jval = (j >= 0);
            const int  jj   = jval ? j : 0;

            const float4 pj = __ldg(&pack[jj]);
            const float dx = __fadd_rn(pi.x, -pj.x);
            const float dy = __fadd_rn(pi.y, -pj.y);
            const float dz = __fadd_rn(pi.z, -pj.z);
            // Reference association (verified R5): (dx^2 + dz^2) + dy^2,
            // fully uncontracted, then * 50.0f (XLA reciprocal of 0.02f).
            const float sxz = __fadd_rn(__fmul_rn(dx, dx), __fmul_rn(dz, dz));
            const float r2  = __fadd_rn(sxz, __fmul_rn(dy, dy));
            const float rr  = __fsqrt_rn(r2);
            const float uu  = __fmul_rn(rr, 50.0f);
            const int   idx = (int)uu;          // trunc, uu >= 0

            const bool  v    = jval && (idx < NSPLINE);
            const int   ci   = min(idx, NSPLINE - 1);
            const float frac = __fadd_rn(uu, -(float)idx);
            const int   tj   = __float_as_int(pj.w);

            const float4 cc = s_tab[tj * NSPLINE + ci];
            float e = fmaf(cc.w, frac, cc.z);
            e = fmaf(e, frac, cc.y);
            e = fmaf(e, frac, cc.x);
            acc += v ? e : 0.0f;
        }

        // Warp reduction
        #pragma unroll
        for (int o = 16; o > 0; o >>= 1)
            acc += __shfl_xor_sync(0xffffffffu, acc, o);

        if (lane == 0)
            out[(size_t)f * NLOC + atom] = 0.5f * acc;
    }
}

extern "C" void kernel_launch(void* const* d_in, const int* in_sizes, int n_in,
                              void* d_out, int out_size)
{
    const float*  coord = (const float*)  d_in[0]; // (8, 8192, 3) f32
    const int*    atype = (const int*)    d_in[1]; // (8, 8192) i32
    const int*    nlist = (const int*)    d_in[2]; // (8, 4096, 256) i32
    const float4* tab   = (const float4*) d_in[3]; // (4, 4, 1024, 4) f32 -> float4
    float*        out   = (float*)        d_out;   // (8, 4096) f32

    const int smem_bytes = NTYPES * NSPLINE * (int)sizeof(float4); // 65536
    static bool attr_set = false;
    if (!attr_set) {
        cudaFuncSetAttribute(pairtab_energy_kernel,
                             cudaFuncAttributeMaxDynamicSharedMemorySize, smem_bytes);
        attr_set = true;
    }

    pack_kernel<<<NFRAMES * 8, 512>>>(coord, atype);
    bin_by_type_kernel<<<NFRAMES, 1024>>>(atype);

    dim3 grid(NTYPES * CHUNKS, NFRAMES);   // (36, 8) = 288 CTAs
    pairtab_energy_kernel<<<grid, THREADS, smem_bytes>>>(nlist, tab, out);
}

// round 15
// speedup vs baseline: 1.3904x; 1.2877x over previous
#include <cuda_runtime.h>
#include <cuda_bf16.h>
#include <cstddef>

// Problem constants (from reference)
#define NFRAMES 8
#define NLOC    4096
#define NALL    8192
#define NNEI    256
#define NTYPES  4
#define NSPLINE 1024

static constexpr int THREADS = 1024; // 32 warps/CTA, 1 CTA/SM (192KB smem)
static constexpr int WARPS   = THREADS / 32;
static constexpr int CHUNKS  = 4;    // chunks per (frame,type) bin -> grid (16,8)=128 CTAs

// Device-global scratch (allocation-free)
__device__ int g_counts[NFRAMES * NTYPES];
__device__ int g_lists [NFRAMES * NTYPES * NLOC];

// ---------------- Pre-pass: bin local atoms by their own type ----------------
__global__ __launch_bounds__(1024, 1)
void bin_by_type_kernel(const int* __restrict__ atype) // (NFRAMES, NALL)
{
    const int f   = blockIdx.x;
    const int tid = threadIdx.x;
    __shared__ int s_off[NTYPES];

    if (tid < NTYPES) s_off[tid] = 0;
    __syncthreads();

    const int* af = atype + (size_t)f * NALL; // local atoms = first NLOC
    for (int a = tid; a < NLOC; a += 1024) {
        const int t    = af[a];
        const int slot = atomicAdd(&s_off[t], 1);
        g_lists[(f * NTYPES + t) * NLOC + slot] = a;
    }
    __syncthreads();
    if (tid < NTYPES)
        g_counts[f * NTYPES + tid] = s_off[tid];
}

// ---------------- Main kernel ----------------
// Dynamic smem: s_pack float4[NALL] (128KB) + s_tab float4[NTYPES*NSPLINE] (64KB)
// 8 lanes per atom, 4 atoms per warp: minimal SHFL/STG/MIO overhead.
__global__ __launch_bounds__(THREADS, 1)
void pairtab_energy_kernel(const float*  __restrict__ coord,   // (NFRAMES, NALL, 3)
                           const int*    __restrict__ atype,   // (NFRAMES, NALL)
                           const int*    __restrict__ nlist,   // (NFRAMES, NLOC, NNEI)
                           const float4* __restrict__ tab,     // (NTYPES,NTYPES,NSPLINE) f4
                           float*        __restrict__ out)     // (NFRAMES, NLOC)
{
    extern __shared__ float4 s_mem[];
    float4* s_pack = s_mem;          // [NALL]
    float4* s_tab  = s_mem + NALL;   // [NTYPES * NSPLINE]

    const int f     = blockIdx.y;
    const int t     = blockIdx.x >> 2;   // i_type this CTA serves
    const int chunk = blockIdx.x & 3;
    const int tid   = threadIdx.x;

    // ---- Stage coords + types of this frame (coalesced) ----
    {
        const float* cf = coord + (size_t)f * NALL * 3;
        const int*   af = atype + (size_t)f * NALL;
        for (int a = tid; a < NALL; a += THREADS) {
            float x = cf[a * 3 + 0];
            float y = cf[a * 3 + 1];
            float z = cf[a * 3 + 2];
            int   ty = af[a];
            s_pack[a] = make_float4(x, y, z, __int_as_float(ty));
        }
    }
    // ---- Stage tab[t] : 64KB (coalesced) ----
    {
        const float4* tf = tab + (size_t)t * NTYPES * NSPLINE;
        for (int i = tid; i < NTYPES * NSPLINE; i += THREADS)
            s_tab[i] = tf[i];
    }
    __syncthreads();

    const int lane = tid & 31;
    const int wid  = tid >> 5;
    const int grp  = lane >> 3;          // 0..3 : which atom in the quad
    const int sub  = lane & 7;           // 0..7 : lane within atom group

    const int  cnt   = g_counts[f * NTYPES + t];
    const int  m     = (cnt + CHUNKS - 1) / CHUNKS;
    const int  start = chunk * m;
    const int  end   = min(start + m, cnt);
    const int* list  = g_lists + (f * NTYPES + t) * NLOC;

    const int4* nlb = reinterpret_cast<const int4*>(nlist)
                    + (size_t)f * NLOC * (NNEI / 4);

    // Each warp iteration consumes 4 atoms (one per 8-lane group).
    for (int k = start + wid * 4; k < end; k += WARPS * 4) {
        const int  ka    = k + grp;
        const bool avalid = (ka < end);
        const int  atom  = list[avalid ? ka : (end - 1)];   // broadcast per group

        const float4 pi = s_pack[atom];                     // 8-lane broadcast LDS
        const int4* nla = nlb + (size_t)atom * (NNEI / 4);

        float acc = 0.0f;

        // 32 neighbors per lane: 8 chunks x int4.
        #pragma unroll
        for (int c = 0; c < 8; ++c) {
            const int4 n4 = nla[c * 8 + sub];   // 128B contiguous per group
            const int js[4] = { n4.x, n4.y, n4.z, n4.w };

            #pragma unroll
            for (int i = 0; i < 4; ++i) {
                const int  j    = js[i];
                const bool jval = (j >= 0);
                const int  jj   = jval ? j : 0;

                const float4 pj = s_pack[jj];
                const float dx = __fadd_rn(pi.x, -pj.x);
                const float dy = __fadd_rn(pi.y, -pj.y);
                const float dz = __fadd_rn(pi.z, -pj.z);
                // Reference association (verified R5): (dx^2 + dz^2) + dy^2,
                // fully uncontracted, then * 50.0f (XLA reciprocal of 0.02f).
                const float sxz = __fadd_rn(__fmul_rn(dx, dx), __fmul_rn(dz, dz));
                const float r2  = __fadd_rn(sxz, __fmul_rn(dy, dy));
                const float rr  = __fsqrt_rn(r2);
                const float uu  = __fmul_rn(rr, 50.0f);
                const int   idx = (int)uu;          // trunc, uu >= 0

                const bool  v    = jval && (idx < NSPLINE);
                const int   ci   = min(idx, NSPLINE - 1);
                const float frac = __fadd_rn(uu, -(float)idx);
                const int   tj   = __float_as_int(pj.w);

                const float4 cc = s_tab[tj * NSPLINE + ci];
                float e = fmaf(cc.w, frac, cc.z);
                e = fmaf(e, frac, cc.y);
                e = fmaf(e, frac, cc.x);
                acc += v ? e : 0.0f;
            }
        }

        // Reduce within each 8-lane group (3 SHFLs total, parallel over groups).
        acc += __shfl_xor_sync(0xffffffffu, acc, 1);
        acc += __shfl_xor_sync(0xffffffffu, acc, 2);
        acc += __shfl_xor_sync(0xffffffffu, acc, 4);

        if (sub == 0 && avalid)
            out[(size_t)f * NLOC + atom] = 0.5f * acc;
    }
}

extern "C" void kernel_launch(void* const* d_in, const int* in_sizes, int n_in,
                              void* d_out, int out_size)
{
    const float*  coord = (const float*)  d_in[0]; // (8, 8192, 3) f32
    const int*    atype = (const int*)    d_in[1]; // (8, 8192) i32
    const int*    nlist = (const int*)    d_in[2]; // (8, 4096, 256) i32
    const float4* tab   = (const float4*) d_in[3]; // (4, 4, 1024, 4) f32 -> float4
    float*        out   = (float*)        d_out;   // (8, 4096) f32

    const int smem_bytes = (NALL + NTYPES * NSPLINE) * (int)sizeof(float4); // 196608
    static bool attr_set = false;
    if (!attr_set) {
        cudaFuncSetAttribute(pairtab_energy_kernel,
                             cudaFuncAttributeMaxDynamicSharedMemorySize, smem_bytes);
        attr_set = true;
    }

    bin_by_type_kernel<<<NFRAMES, 1024>>>(atype);

    dim3 grid(NTYPES * CHUNKS, NFRAMES);   // (16, 8) = 128 CTAs
    pairtab_energy_kernel<<<grid, THREADS, smem_bytes>>>(coord, atype, nlist, tab, out);
}

// round 16
// speedup vs baseline: 1.3916x; 1.0009x over previous
#include <cuda_runtime.h>
#include <cuda_bf16.h>
#include <cstddef>

// Problem constants (from reference)
#define NFRAMES 8
#define NLOC    4096
#define NALL    8192
#define NNEI    256
#define NTYPES  4
#define NSPLINE 1024

#define TROW (NSPLINE + 1)   // padded table row: entry [1024] = zeros

static constexpr int THREADS = 1024; // 32 warps/CTA, 1 CTA/SM
static constexpr int WARPS   = THREADS / 32;
static constexpr int CHUNKS  = 4;    // grid (16,8) = 128 CTAs

// Device-global scratch (allocation-free)
__device__ int g_counts[NFRAMES * NTYPES];
__device__ int g_lists [NFRAMES * NTYPES * NLOC];

// ---------------- Pre-pass: bin local atoms by their own type ----------------
__global__ __launch_bounds__(1024, 1)
void bin_by_type_kernel(const int* __restrict__ atype) // (NFRAMES, NALL)
{
    const int f   = blockIdx.x;
    const int tid = threadIdx.x;
    __shared__ int s_off[NTYPES];

    if (tid < NTYPES) s_off[tid] = 0;
    __syncthreads();

    const int* af = atype + (size_t)f * NALL; // local atoms = first NLOC
    for (int a = tid; a < NLOC; a += 1024) {
        const int t    = af[a];
        const int slot = atomicAdd(&s_off[t], 1);
        g_lists[(f * NTYPES + t) * NLOC + slot] = a;
    }
    __syncthreads();
    if (tid < NTYPES)
        g_counts[f * NTYPES + tid] = s_off[tid];
}

// ---------------- Main kernel ----------------
// smem: s_pack float4[NALL+1] (sentinel at NALL) + s_tab float4[NTYPES*TROW]
// (zero row at index 1024 of each type-row). Total 196,688 B -> 1 CTA/SM.
__global__ __launch_bounds__(THREADS, 1)
void pairtab_energy_kernel(const float*  __restrict__ coord,   // (NFRAMES, NALL, 3)
                           const int*    __restrict__ atype,   // (NFRAMES, NALL)
                           const int*    __restrict__ nlist,   // (NFRAMES, NLOC, NNEI)
                           const float4* __restrict__ tab,     // (NTYPES,NTYPES,NSPLINE) f4
                           float*        __restrict__ out)     // (NFRAMES, NLOC)
{
    extern __shared__ float4 s_mem[];
    float4* s_pack = s_mem;                // [NALL + 1]
    float4* s_tab  = s_mem + (NALL + 1);   // [NTYPES * TROW]

    const int f     = blockIdx.y;
    const int t     = blockIdx.x >> 2;   // i_type this CTA serves
    const int chunk = blockIdx.x & 3;
    const int tid   = threadIdx.x;

    // ---- Stage coords + premultiplied j-row base (coalesced) ----
    {
        const float* cf = coord + (size_t)f * NALL * 3;
        const int*   af = atype + (size_t)f * NALL;
        for (int a = tid; a < NALL; a += THREADS) {
            float x = cf[a * 3 + 0];
            float y = cf[a * 3 + 1];
            float z = cf[a * 3 + 2];
            int   w = af[a] * TROW;      // tj * (NSPLINE+1), premultiplied
            s_pack[a] = make_float4(x, y, z, __int_as_float(w));
        }
        if (tid == 0)  // sentinel: invalid neighbors land here -> idx saturates
            s_pack[NALL] = make_float4(1.0e15f, 1.0e15f, 1.0e15f,
                                       __int_as_float(0));
    }
    // ---- Stage tab[t] with a zero row per tj (stride TROW) ----
    {
        const float4* tf = tab + (size_t)t * NTYPES * NSPLINE;
        for (int r = 0; r < NTYPES; ++r) {
            for (int e = tid; e < TROW; e += THREADS) {
                s_tab[r * TROW + e] = (e < NSPLINE)
                    ? tf[r * NSPLINE + e]
                    : make_float4(0.f, 0.f, 0.f, 0.f);
            }
        }
    }
    __syncthreads();

    const int lane = tid & 31;
    const int wid  = tid >> 5;
    const int grp  = lane >> 3;          // 0..3 : which atom in the quad
    const int sub  = lane & 7;           // 0..7 : lane within atom group

    const int  cnt   = g_counts[f * NTYPES + t];
    const int  m     = (cnt + CHUNKS - 1) / CHUNKS;
    const int  start = chunk * m;
    const int  end   = min(start + m, cnt);
    const int* list  = g_lists + (f * NTYPES + t) * NLOC;

    const int4* nlb = reinterpret_cast<const int4*>(nlist)
                    + (size_t)f * NLOC * (NNEI / 4);

    // Each warp iteration consumes 4 atoms (one per 8-lane group).
    for (int k = start + wid * 4; k < end; k += WARPS * 4) {
        const int  ka     = k + grp;
        const bool avalid = (ka < end);
        const int  atom   = list[avalid ? ka : (end - 1)];

        const float4 pi = s_pack[atom];                     // 8-lane broadcast
        const int4* nla = nlb + (size_t)atom * (NNEI / 4);

        float acc = 0.0f;

        // 32 neighbors per lane: 8 chunks x int4.
        #pragma unroll
        for (int c = 0; c < 8; ++c) {
            const int4 n4 = nla[c * 8 + sub];   // 128B contiguous per group
            const int js[4] = { n4.x, n4.y, n4.z, n4.w };

            #pragma unroll
            for (int i = 0; i < 4; ++i) {
                // j < 0 -> unsigned huge -> min gives sentinel NALL
                const unsigned jj = min((unsigned)js[i], (unsigned)NALL);

                const float4 pj = s_pack[jj];
                const float dx = __fadd_rn(pi.x, -pj.x);
                const float dy = __fadd_rn(pi.y, -pj.y);
                const float dz = __fadd_rn(pi.z, -pj.z);
                // Reference association (verified R5): (dx^2 + dz^2) + dy^2,
                // fully uncontracted, then * 50.0f (XLA reciprocal of 0.02f).
                const float sxz = __fadd_rn(__fmul_rn(dx, dx), __fmul_rn(dz, dz));
                const float r2  = __fadd_rn(sxz, __fmul_rn(dy, dy));
                const float rr  = __fsqrt_rn(r2);
                const float uu  = __fmul_rn(rr, 50.0f);
                const int   idx = (int)uu;           // trunc; saturates for sentinel

                const int   ci   = min(idx, NSPLINE); // 1024 -> zero row
                const float frac = __fadd_rn(uu, -(float)idx);

                const float4 cc = s_tab[__float_as_int(pj.w) + ci];
                float e = fmaf(cc.w, frac, cc.z);
                e = fmaf(e, frac, cc.y);
                e = fmaf(e, frac, cc.x);
                acc += e;                             // zero row -> e == 0
            }
        }

        // Reduce within each 8-lane group (3 SHFLs, parallel over groups).
        acc += __shfl_xor_sync(0xffffffffu, acc, 1);
        acc += __shfl_xor_sync(0xffffffffu, acc, 2);
        acc += __shfl_xor_sync(0xffffffffu, acc, 4);

        if (sub == 0 && avalid)
            out[(size_t)f * NLOC + atom] = 0.5f * acc;
    }
}

extern "C" void kernel_launch(void* const* d_in, const int* in_sizes, int n_in,
                              void* d_out, int out_size)
{
    const float*  coord = (const float*)  d_in[0]; // (8, 8192, 3) f32
    const int*    atype = (const int*)    d_in[1]; // (8, 8192) i32
    const int*    nlist = (const int*)    d_in[2]; // (8, 4096, 256) i32
    const float4* tab   = (const float4*) d_in[3]; // (4, 4, 1024, 4) f32 -> float4
    float*        out   = (float*)        d_out;   // (8, 4096) f32

    const int smem_bytes = (NALL + 1 + NTYPES * TROW) * (int)sizeof(float4); // 196688
    static bool attr_set = false;
    if (!attr_set) {
        cudaFuncSetAttribute(pairtab_energy_kernel,
                             cudaFuncAttributeMaxDynamicSharedMemorySize, smem_bytes);
        attr_set = true;
    }

    bin_by_type_kernel<<<NFRAMES, 1024>>>(atype);

    dim3 grid(NTYPES * CHUNKS, NFRAMES);   // (16, 8) = 128 CTAs
    pairtab_energy_kernel<<<grid, THREADS, smem_bytes>>>(coord, atype, nlist, tab, out);
}